// round 10
// baseline (speedup 1.0000x reference)
#include <cuda_runtime.h>
#include <cstdint>

#define N_ROWS 8192
#define O_COLS 4096
#define K_DIM  4096
#define KWORDS 128          // K_DIM / 32

// ---- scratch (device globals; no dynamic allocation allowed) ----
__device__ __align__(16) unsigned xp_g[(size_t)N_ROWS * KWORDS];   // 4 MB
__device__ __align__(16) unsigned wp_g[(size_t)O_COLS * KWORDS];   // 2 MB
__device__ float psum_g[N_ROWS];
__device__ float mean_g;

// ============================================================
// Pack x rows into sign bits (bit=1 iff negative) + |x| row sums.
// ============================================================
__global__ void pack_x_kernel(const float* __restrict__ x) {
    const int row  = blockIdx.x;
    const int tid  = threadIdx.x;
    const int lane = tid & 31;
    const int warp = tid >> 5;

    const float* xr = x + (size_t)row * K_DIM;
    float s = 0.f;

    #pragma unroll 4
    for (int it = 0; it < 32; it++) {
        const int w = warp * 32 + it;
        const float v = xr[w * 32 + lane];
        s += fabsf(v);
        const unsigned bits = __ballot_sync(0xffffffffu, __float_as_uint(v) >> 31);
        if (lane == 0) xp_g[(size_t)row * KWORDS + w] = bits;
    }

    __shared__ float red[128];
    red[tid] = s;
    __syncthreads();
    #pragma unroll
    for (int off = 64; off > 0; off >>= 1) {
        if (tid < off) red[tid] += red[tid + off];
        __syncthreads();
    }
    if (tid == 0) psum_g[row] = red[0];
}

__global__ void pack_w_kernel(const float* __restrict__ W) {
    const int row  = blockIdx.x;
    const int tid  = threadIdx.x;
    const int lane = tid & 31;
    const int warp = tid >> 5;

    const float* wr = W + (size_t)row * K_DIM;

    #pragma unroll 4
    for (int it = 0; it < 32; it++) {
        const int w = warp * 32 + it;
        const float v = wr[w * 32 + lane];
        const unsigned bits = __ballot_sync(0xffffffffu, __float_as_uint(v) >> 31);
        if (lane == 0) wp_g[(size_t)row * KWORDS + w] = bits;
    }
}

__global__ void reduce_mean_kernel() {
    __shared__ float red[1024];
    const int tid = threadIdx.x;
    float s = 0.f;
    for (int i = tid; i < N_ROWS; i += 1024) s += psum_g[i];
    red[tid] = s;
    __syncthreads();
    #pragma unroll
    for (int off = 512; off > 0; off >>= 1) {
        if (tid < off) red[tid] += red[tid + off];
        __syncthreads();
    }
    if (tid == 0) mean_g = red[0] * (1.0f / ((float)N_ROWS * (float)K_DIM));
}

// ============================================================
// XNOR-popcount GEMM v3: double-buffered smem, register prefetch.
// 64x64 tile, 256 threads, 4(m) x 4(o) per thread, packed dual accs.
// One __syncthreads per K-chunk; LDG for chunk c+1 overlaps compute of c.
// ============================================================
#define BT 64
#define KW 16
#define NCH (KWORDS / KW)    // 8
#define KPAD 68

__device__ __forceinline__ int imad_pack(int hi, int sh, int lo) {
    int r;
    asm("mad.lo.s32 %0, %1, %2, %3;" : "=r"(r) : "r"(hi), "r"(sh), "r"(lo));
    return r;
}

__global__ __launch_bounds__(256, 4)
void bgemm_kernel(const float* __restrict__ b, float* __restrict__ out) {
    __shared__ __align__(16) unsigned xs[2][KW][KPAD];
    __shared__ __align__(16) unsigned ws[2][KW][KPAD];

    const int tid = threadIdx.x;
    const int tx  = tid & 15;
    const int ty  = tid >> 4;
    const int o0  = blockIdx.x * BT;
    const int n0  = blockIdx.y * BT;

    const int lrow = tid >> 2;
    const int lq   = tid & 3;

    const unsigned* gx = &xp_g[(size_t)(n0 + lrow) * KWORDS + lq * 4];
    const unsigned* gw = &wp_g[(size_t)(o0 + lrow) * KWORDS + lq * 4];

    int sh;   // 0x10000 in a register, opaque to constant folding
    asm("mov.b32 %0, 0x10000;" : "=r"(sh));

    // accP[i][j2]: lo16 = count(col 2*j2), hi16 = count(col 2*j2+1)
    int accP[4][2];
    #pragma unroll
    for (int i = 0; i < 4; i++) { accP[i][0] = 0; accP[i][1] = 0; }

    // prologue: chunk 0 -> buffer 0
    uint4 xv = *(const uint4*)(gx + 0);
    uint4 wv = *(const uint4*)(gw + 0);
    xs[0][lq * 4 + 0][lrow] = xv.x;
    xs[0][lq * 4 + 1][lrow] = xv.y;
    xs[0][lq * 4 + 2][lrow] = xv.z;
    xs[0][lq * 4 + 3][lrow] = xv.w;
    ws[0][lq * 4 + 0][lrow] = wv.x;
    ws[0][lq * 4 + 1][lrow] = wv.y;
    ws[0][lq * 4 + 2][lrow] = wv.z;
    ws[0][lq * 4 + 3][lrow] = wv.w;
    __syncthreads();

    #pragma unroll 1
    for (int c = 0; c < NCH; c++) {
        const int cur = c & 1;

        // prefetch chunk c+1 into registers (latency hidden by compute below)
        if (c + 1 < NCH) {
            xv = *(const uint4*)(gx + (c + 1) * KW);
            wv = *(const uint4*)(gw + (c + 1) * KW);
        }

        // compute chunk c from buffer cur
        #pragma unroll
        for (int k = 0; k < KW; k += 2) {
            const uint4 a0 = *(const uint4*)&xs[cur][k][ty * 4];
            const uint4 c0 = *(const uint4*)&ws[cur][k][tx * 4];
            const uint4 a1 = *(const uint4*)&xs[cur][k + 1][ty * 4];
            const uint4 c1 = *(const uint4*)&ws[cur][k + 1][tx * 4];

            const unsigned ar0[4] = {a0.x, a0.y, a0.z, a0.w};
            const unsigned ar1[4] = {a1.x, a1.y, a1.z, a1.w};
            const unsigned cr0[4] = {c0.x, c0.y, c0.z, c0.w};
            const unsigned cr1[4] = {c1.x, c1.y, c1.z, c1.w};

            #pragma unroll
            for (int i = 0; i < 4; i++) {
                #pragma unroll
                for (int j2 = 0; j2 < 2; j2++) {
                    const int p0lo = __popc(ar0[i] ^ cr0[j2 * 2 + 0]);
                    const int p0hi = __popc(ar0[i] ^ cr0[j2 * 2 + 1]);
                    const int p1lo = __popc(ar1[i] ^ cr1[j2 * 2 + 0]);
                    const int p1hi = __popc(ar1[i] ^ cr1[j2 * 2 + 1]);
                    const int pc0 = imad_pack(p0hi, sh, p0lo);
                    const int pc1 = imad_pack(p1hi, sh, p1lo);
                    accP[i][j2] += pc0 + pc1;       // IADD3
                }
            }
        }

        // stage chunk c+1 into the opposite buffer; one barrier per chunk
        if (c + 1 < NCH) {
            const int nxt = cur ^ 1;
            xs[nxt][lq * 4 + 0][lrow] = xv.x;
            xs[nxt][lq * 4 + 1][lrow] = xv.y;
            xs[nxt][lq * 4 + 2][lrow] = xv.z;
            xs[nxt][lq * 4 + 3][lrow] = xv.w;
            ws[nxt][lq * 4 + 0][lrow] = wv.x;
            ws[nxt][lq * 4 + 1][lrow] = wv.y;
            ws[nxt][lq * 4 + 2][lrow] = wv.z;
            ws[nxt][lq * 4 + 3][lrow] = wv.w;
            __syncthreads();
        }
    }

    const float mean = mean_g;
    const int o_base = o0 + tx * 4;
    const int n_base = n0 + ty * 4;
    const float4 bb = *(const float4*)&b[o_base];

    #pragma unroll
    for (int i = 0; i < 4; i++) {
        const int c0 = accP[i][0] & 0xFFFF;
        const int c1 = (unsigned)accP[i][0] >> 16;
        const int c2 = accP[i][1] & 0xFFFF;
        const int c3 = (unsigned)accP[i][1] >> 16;
        float4 r;
        r.x = ((float)(K_DIM - 2 * c0) + bb.x) * mean;
        r.y = ((float)(K_DIM - 2 * c1) + bb.y) * mean;
        r.z = ((float)(K_DIM - 2 * c2) + bb.z) * mean;
        r.w = ((float)(K_DIM - 2 * c3) + bb.w) * mean;
        *(float4*)&out[(size_t)(n_base + i) * O_COLS + o_base] = r;
    }
}

// ============================================================
// launch: pack -> mean -> gemm (stream-ordered, graph-capturable)
// ============================================================
extern "C" void kernel_launch(void* const* d_in, const int* in_sizes, int n_in,
                              void* d_out, int out_size) {
    const float* x = (const float*)d_in[0];   // [8192, 4096]
    const float* W = (const float*)d_in[1];   // [4096, 4096]
    const float* b = (const float*)d_in[2];   // [4096]
    float* out = (float*)d_out;

    pack_x_kernel<<<N_ROWS, 128>>>(x);
    pack_w_kernel<<<O_COLS, 128>>>(W);
    reduce_mean_kernel<<<1, 1024>>>();

    dim3 grid(O_COLS / BT, N_ROWS / BT);      // (64, 128)
    bgemm_kernel<<<grid, 256>>>(b, out);
}